// round 5
// baseline (speedup 1.0000x reference)
#include <cuda_runtime.h>
#include <cstdint>

#define HH 1024
#define WW 1024
#define NPIX (HH*WW)
#define C_IN 8
#define C_HID 32
#define NIT 64
#define TW 16
#define TH 32

typedef unsigned long long u64;

// Ping-pong state (64 MB) + precomputed dropout masks (8 MB), static device scratch.
__device__ float g_x[2][C_IN][NPIX];
__device__ unsigned g_mask[NIT][NPIX/32];

// ---------------- packed f32x2 helpers ----------------
__device__ __forceinline__ u64 fma2(u64 a, u64 b, u64 c) {
    u64 d;
    asm("fma.rn.f32x2 %0, %1, %2, %3;" : "=l"(d) : "l"(a), "l"(b), "l"(c));
    return d;
}
__device__ __forceinline__ u64 dup2(float x) {
    u64 r;
    asm("mov.b64 %0, {%1, %1};" : "=l"(r) : "f"(x));
    return r;
}
__device__ __forceinline__ void unpack2(u64 v, float& lo, float& hi) {
    asm("mov.b64 {%0, %1}, %2;" : "=f"(lo), "=f"(hi) : "l"(v));
}

// ---------------- threefry2x32 (exact JAX semantics) ----------------
__device__ __forceinline__ uint32_t rotl32(uint32_t x, int d) {
    return (x << d) | (x >> (32 - d));
}
__device__ __forceinline__ void tf_round(uint32_t& x0, uint32_t& x1, int r) {
    x0 += x1; x1 = rotl32(x1, r); x1 ^= x0;
}
__device__ __forceinline__ uint2 threefry(uint32_t k0, uint32_t k1, uint32_t x0, uint32_t x1) {
    uint32_t k2 = k0 ^ k1 ^ 0x1BD11BDAu;
    x0 += k0; x1 += k1;
    tf_round(x0,x1,13); tf_round(x0,x1,15); tf_round(x0,x1,26); tf_round(x0,x1,6);
    x0 += k1; x1 += k2 + 1u;
    tf_round(x0,x1,17); tf_round(x0,x1,29); tf_round(x0,x1,16); tf_round(x0,x1,24);
    x0 += k2; x1 += k0 + 2u;
    tf_round(x0,x1,13); tf_round(x0,x1,15); tf_round(x0,x1,26); tf_round(x0,x1,6);
    x0 += k0; x1 += k1 + 3u;
    tf_round(x0,x1,17); tf_round(x0,x1,29); tf_round(x0,x1,16); tf_round(x0,x1,24);
    x0 += k1; x1 += k2 + 4u;
    tf_round(x0,x1,13); tf_round(x0,x1,15); tf_round(x0,x1,26); tf_round(x0,x1,6);
    x0 += k2; x1 += k0 + 5u;
    return make_uint2(x0, x1);
}

// ---------------- mask precompute (jax_threefry_partitionable=True) ----------------
__global__ void genmask_kernel() {
    int gid = blockIdx.x * blockDim.x + threadIdx.x;   // NIT * 32768 threads; 32 pixels each
    int t  = gid >> 15;
    int wq = gid & 32767;
    uint2 kt = threefry(0u, 42u, 0u, (uint32_t)t);
    unsigned m = 0u;
    unsigned base = (unsigned)wq * 32u;
    #pragma unroll 4
    for (int k = 0; k < 32; k++) {
        uint2 rv = threefry(kt.x, kt.y, 0u, base + (unsigned)k);
        uint32_t bits = rv.x ^ rv.y;
        if ((bits >> 9) > 0x400000u) m |= (1u << k);
    }
    g_mask[t][wq] = m;
}

// ---------------- bilinear upsample 8x8 -> 1024x1024 ----------------
__global__ void upsample_kernel(const float* __restrict__ seed) {
    int i = blockIdx.x * blockDim.x + threadIdx.x;
    if (i >= C_IN * NPIX) return;
    int ch = i / NPIX;
    int p  = i % NPIX;
    int r = p / WW, c = p % WW;
    float sr = (r + 0.5f) * (8.0f / HH) - 0.5f;
    float sc = (c + 0.5f) * (8.0f / WW) - 0.5f;
    float fr0 = floorf(sr), fc0 = floorf(sc);
    float fr = sr - fr0,    fc = sc - fc0;
    int r0 = (int)fr0, c0 = (int)fc0;
    int r1 = min(r0 + 1, 7), c1 = min(c0 + 1, 7);
    r0 = max(r0, 0); c0 = max(c0, 0);
    const float* s = seed + ch * 64;
    float v00 = s[r0*8 + c0], v01 = s[r0*8 + c1];
    float v10 = s[r1*8 + c0], v11 = s[r1*8 + c1];
    float v0 = v00 * (1.0f - fc) + v01 * fc;
    float v1 = v10 * (1.0f - fc) + v11 * fc;
    g_x[0][ch][p] = v0 * (1.0f - fr) + v1 * fr;
}

// ---------------- one NCA step: 2 vertical pixels per thread, f32x2 over channels ----------------
// Tile: 16 wide x 32 tall per block of 256 threads. Each thread owns pixels
// (row0 + 2q, col) and (row0 + 2q + 1, col), q = tid/16.
#define TSTRIDE 24   // 2*TSTRIDE % 32 == 16 -> the two lane-groups hit disjoint banks

__global__ __launch_bounds__(256) void step_kernel(
    const float* __restrict__ W1, const float* __restrict__ b1,
    const float* __restrict__ W2, const float* __restrict__ b2,
    int src, int iter)
{
    __shared__ __align__(16) float w1s[72 * 32];     // [tap][out ch], 128B rows
    __shared__ __align__(16) float w2s[32 * 8];      // [hid][out ch]
    __shared__ __align__(16) float b1s[32];
    __shared__ __align__(16) float b2s[8];
    __shared__ float tile[C_IN][TH + 2][TSTRIDE];    // valid cols [0,18)

    int tid = threadIdx.x;
    for (int i = tid; i < 2304; i += 256) {
        int o = i / 72, t = i % 72;
        w1s[t * 32 + o] = W1[i];                     // W1 OIHW -> [tap][o]
    }
    {
        int o = tid / 32, c = tid % 32;              // 256 threads cover 8*32
        w2s[c * 8 + o] = W2[tid];                    // W2: [o][c]
    }
    if (tid < 32) b1s[tid] = b1[tid];
    if (tid < 8)  b2s[tid] = b2[tid];

    int col0 = blockIdx.x * TW;
    int row0 = blockIdx.y * TH;

    // load (TH+2) x 18 halo tile per channel (zero-pad outside)
    for (int i = tid; i < C_IN * (TH + 2) * 18; i += 256) {
        int ch = i / ((TH + 2) * 18);
        int rem = i % ((TH + 2) * 18);
        int r  = rem / 18;
        int c  = rem % 18;
        int gr = row0 + r - 1, gc = col0 + c - 1;
        float v = 0.0f;
        if ((unsigned)gr < HH && (unsigned)gc < WW)
            v = g_x[src][ch][gr * WW + gc];
        tile[ch][r][c] = v;
    }
    __syncthreads();

    int tx = tid % TW;
    int q  = tid / TW;            // 0..15
    int rl = 2 * q;               // local row of pixel 0 (tile row index = rl + ky)

    // ---- conv3x3: 2 pixels x 16 packed accumulators ----
    u64 acc0[16], acc1[16];
    {
        const ulonglong2* bp = (const ulonglong2*)b1s;
        #pragma unroll
        for (int k = 0; k < 8; k++) {
            ulonglong2 v = bp[k];
            acc0[2*k] = v.x; acc0[2*k+1] = v.y;
            acc1[2*k] = v.x; acc1[2*k+1] = v.y;
        }
    }

    #pragma unroll 1
    for (int ci = 0; ci < C_IN; ci++) {
        // 4 rows x 3 cols of x feed both pixels' 3x3 windows
        float xr[4][3];
        #pragma unroll
        for (int r = 0; r < 4; r++) {
            #pragma unroll
            for (int c = 0; c < 3; c++)
                xr[r][c] = tile[ci][rl + r][tx + c];
        }
        #pragma unroll
        for (int ky = 0; ky < 3; ky++) {
            #pragma unroll
            for (int kx = 0; kx < 3; kx++) {
                u64 x0 = dup2(xr[ky][kx]);
                u64 x1 = dup2(xr[ky + 1][kx]);
                const ulonglong2* wp = (const ulonglong2*)&w1s[(ci * 9 + ky * 3 + kx) * 32];
                #pragma unroll
                for (int j = 0; j < 8; j++) {
                    ulonglong2 w = wp[j];            // LDS.128 broadcast: 4 weights -> 2 pixels
                    acc0[2*j]   = fma2(x0, w.x, acc0[2*j]);
                    acc0[2*j+1] = fma2(x0, w.y, acc0[2*j+1]);
                    acc1[2*j]   = fma2(x1, w.x, acc1[2*j]);
                    acc1[2*j+1] = fma2(x1, w.y, acc1[2*j+1]);
                }
            }
        }
    }

    // ---- gelu (exact erf) + conv1x1 + masked update, per pixel ----
    int col = col0 + tx;
    #pragma unroll
    for (int s = 0; s < 2; s++) {
        u64* acc = s ? acc1 : acc0;
        u64 dxp[4];
        {
            const ulonglong2* bp = (const ulonglong2*)b2s;
            ulonglong2 v0 = bp[0], v1 = bp[1];
            dxp[0] = v0.x; dxp[1] = v0.y; dxp[2] = v1.x; dxp[3] = v1.y;
        }
        #pragma unroll
        for (int j = 0; j < 16; j++) {
            float h0, h1;
            unpack2(acc[j], h0, h1);
            float g0 = 0.5f * h0 * (1.0f + erff(h0 * 0.7071067811865476f));
            float g1 = 0.5f * h1 * (1.0f + erff(h1 * 0.7071067811865476f));
            u64 g0d = dup2(g0), g1d = dup2(g1);
            {
                const ulonglong2* wp = (const ulonglong2*)&w2s[(2*j) * 8];
                ulonglong2 wa = wp[0], wb = wp[1];
                dxp[0] = fma2(g0d, wa.x, dxp[0]);
                dxp[1] = fma2(g0d, wa.y, dxp[1]);
                dxp[2] = fma2(g0d, wb.x, dxp[2]);
                dxp[3] = fma2(g0d, wb.y, dxp[3]);
            }
            {
                const ulonglong2* wp = (const ulonglong2*)&w2s[(2*j+1) * 8];
                ulonglong2 wa = wp[0], wb = wp[1];
                dxp[0] = fma2(g1d, wa.x, dxp[0]);
                dxp[1] = fma2(g1d, wa.y, dxp[1]);
                dxp[2] = fma2(g1d, wb.x, dxp[2]);
                dxp[3] = fma2(g1d, wb.y, dxp[3]);
            }
        }

        int row = row0 + rl + s;
        int p = row * WW + col;
        unsigned bits = g_mask[iter][p >> 5];
        float m = ((bits >> (p & 31)) & 1u) ? 0.1f : 0.0f;   // fold 0.1 into the mask
        int dst = src ^ 1;
        #pragma unroll
        for (int k = 0; k < 4; k++) {
            float d0, d1;
            unpack2(dxp[k], d0, d1);
            g_x[dst][2*k][p]   = tile[2*k][rl + 1 + s][tx + 1]   + d0 * m;
            g_x[dst][2*k+1][p] = tile[2*k+1][rl + 1 + s][tx + 1] + d1 * m;
        }
    }
}

// ---------------- projection ----------------
__global__ void project_kernel(const float* __restrict__ Wp, const float* __restrict__ bp,
                               float* __restrict__ out) {
    int p = blockIdx.x * blockDim.x + threadIdx.x;
    if (p >= NPIX) return;
    float s = bp[0];
    #pragma unroll
    for (int ch = 0; ch < C_IN; ch++) s += g_x[0][ch][p] * Wp[ch];
    out[p] = s;
}

extern "C" void kernel_launch(void* const* d_in, const int* in_sizes, int n_in,
                              void* d_out, int out_size) {
    const float* seed = (const float*)d_in[0];
    const float* W1   = (const float*)d_in[1];
    const float* b1   = (const float*)d_in[2];
    const float* W2   = (const float*)d_in[3];
    const float* b2   = (const float*)d_in[4];
    const float* Wp   = (const float*)d_in[5];
    const float* bp   = (const float*)d_in[6];
    float* out = (float*)d_out;

    upsample_kernel<<<(C_IN * NPIX + 255) / 256, 256>>>(seed);
    genmask_kernel<<<(NIT * 32768) / 256, 256>>>();

    dim3 grid(WW / TW, HH / TH);
    for (int s = 0; s < NIT; s++)
        step_kernel<<<grid, 256>>>(W1, b1, W2, b2, s & 1, s);
    // after 64 steps the result is back in buffer 0
    project_kernel<<<(NPIX + 255) / 256, 256>>>(Wp, bp, out);
}

// round 6
// speedup vs baseline: 1.9148x; 1.9148x over previous
#include <cuda_runtime.h>
#include <cstdint>

#define HH 1024
#define WW 1024
#define NPIX (HH*WW)
#define C_IN 8
#define C_HID 32
#define NIT 64
#define TILE 16

typedef unsigned long long u64;

// Ping-pong state (64 MB) + masks (8 MB) + weight repack staging, static device scratch.
__device__ float g_x[2][C_IN][NPIX];
__device__ unsigned g_mask[NIT][NPIX/32];
__device__ float g_pack[2304 + 256 + 32 + 8];

// Packed weights in constant memory: [tap][o] w1, [hid][o] w2, b1, b2.
#define W1P 0
#define W2P 2304
#define B1P 2560
#define B2P 2592
__constant__ __align__(16) float c_pack[2304 + 256 + 32 + 8];

// ---------------- packed f32x2 helpers ----------------
__device__ __forceinline__ u64 fma2(u64 a, u64 b, u64 c) {
    u64 d;
    asm("fma.rn.f32x2 %0, %1, %2, %3;" : "=l"(d) : "l"(a), "l"(b), "l"(c));
    return d;
}
__device__ __forceinline__ u64 dup2(float x) {
    u64 r;
    asm("mov.b64 %0, {%1, %1};" : "=l"(r) : "f"(x));
    return r;
}
__device__ __forceinline__ void unpack2(u64 v, float& lo, float& hi) {
    asm("mov.b64 {%0, %1}, %2;" : "=f"(lo), "=f"(hi) : "l"(v));
}

// ---------------- threefry2x32 (exact JAX semantics) ----------------
__device__ __forceinline__ uint32_t rotl32(uint32_t x, int d) {
    return (x << d) | (x >> (32 - d));
}
__device__ __forceinline__ void tf_round(uint32_t& x0, uint32_t& x1, int r) {
    x0 += x1; x1 = rotl32(x1, r); x1 ^= x0;
}
__device__ __forceinline__ uint2 threefry(uint32_t k0, uint32_t k1, uint32_t x0, uint32_t x1) {
    uint32_t k2 = k0 ^ k1 ^ 0x1BD11BDAu;
    x0 += k0; x1 += k1;
    tf_round(x0,x1,13); tf_round(x0,x1,15); tf_round(x0,x1,26); tf_round(x0,x1,6);
    x0 += k1; x1 += k2 + 1u;
    tf_round(x0,x1,17); tf_round(x0,x1,29); tf_round(x0,x1,16); tf_round(x0,x1,24);
    x0 += k2; x1 += k0 + 2u;
    tf_round(x0,x1,13); tf_round(x0,x1,15); tf_round(x0,x1,26); tf_round(x0,x1,6);
    x0 += k0; x1 += k1 + 3u;
    tf_round(x0,x1,17); tf_round(x0,x1,29); tf_round(x0,x1,16); tf_round(x0,x1,24);
    x0 += k1; x1 += k2 + 4u;
    tf_round(x0,x1,13); tf_round(x0,x1,15); tf_round(x0,x1,26); tf_round(x0,x1,6);
    x0 += k2; x1 += k0 + 5u;
    return make_uint2(x0, x1);
}

// ---------------- weight repack: OIHW -> [tap][o] (then D2D-copied into c_pack) ----------------
__global__ void repack_kernel(const float* __restrict__ W1, const float* __restrict__ b1,
                              const float* __restrict__ W2, const float* __restrict__ b2) {
    int i = blockIdx.x * blockDim.x + threadIdx.x;   // 2600 items
    if (i < 2304) {
        int o = i / 72, t = i % 72;
        g_pack[W1P + t * 32 + o] = W1[i];
    } else if (i < 2304 + 256) {
        int j = i - 2304;                            // W2: [o][c] -> [c][o]
        int o = j / 32, c = j % 32;
        g_pack[W2P + c * 8 + o] = W2[j];
    } else if (i < 2304 + 256 + 32) {
        g_pack[B1P + (i - 2560)] = b1[i - 2560];
    } else if (i < 2304 + 256 + 32 + 8) {
        g_pack[B2P + (i - 2592)] = b2[i - 2592];
    }
}

// ---------------- mask precompute (jax_threefry_partitionable=True) ----------------
__global__ void genmask_kernel() {
    int gid = blockIdx.x * blockDim.x + threadIdx.x;   // NIT * 32768 threads; 32 pixels each
    int t  = gid >> 15;
    int wq = gid & 32767;
    uint2 kt = threefry(0u, 42u, 0u, (uint32_t)t);
    unsigned m = 0u;
    unsigned base = (unsigned)wq * 32u;
    #pragma unroll 4
    for (int k = 0; k < 32; k++) {
        uint2 rv = threefry(kt.x, kt.y, 0u, base + (unsigned)k);
        uint32_t bits = rv.x ^ rv.y;
        if ((bits >> 9) > 0x400000u) m |= (1u << k);
    }
    g_mask[t][wq] = m;
}

// ---------------- bilinear upsample 8x8 -> 1024x1024 ----------------
__global__ void upsample_kernel(const float* __restrict__ seed) {
    int i = blockIdx.x * blockDim.x + threadIdx.x;
    if (i >= C_IN * NPIX) return;
    int ch = i / NPIX;
    int p  = i % NPIX;
    int r = p / WW, c = p % WW;
    float sr = (r + 0.5f) * (8.0f / HH) - 0.5f;
    float sc = (c + 0.5f) * (8.0f / WW) - 0.5f;
    float fr0 = floorf(sr), fc0 = floorf(sc);
    float fr = sr - fr0,    fc = sc - fc0;
    int r0 = (int)fr0, c0 = (int)fc0;
    int r1 = min(r0 + 1, 7), c1 = min(c0 + 1, 7);
    r0 = max(r0, 0); c0 = max(c0, 0);
    const float* s = seed + ch * 64;
    float v00 = s[r0*8 + c0], v01 = s[r0*8 + c1];
    float v10 = s[r1*8 + c0], v11 = s[r1*8 + c1];
    float v0 = v00 * (1.0f - fc) + v01 * fc;
    float v1 = v10 * (1.0f - fc) + v11 * fc;
    g_x[0][ch][p] = v0 * (1.0f - fr) + v1 * fr;
}

// ---------------- one NCA step: weights via constant port, x tile via smem ----------------
__global__ __launch_bounds__(256) void step_kernel(int src, int iter)
{
    __shared__ float tile[C_IN][TILE + 2][TILE + 3];

    int tid = threadIdx.x;
    int col0 = blockIdx.x * TILE;
    int row0 = blockIdx.y * TILE;

    // load 18x18 halo tile per channel (zero-pad outside)
    for (int i = tid; i < C_IN * 18 * 18; i += 256) {
        int ch = i / (18 * 18);
        int r  = (i / 18) % 18;
        int c  = i % 18;
        int gr = row0 + r - 1, gc = col0 + c - 1;
        float v = 0.0f;
        if ((unsigned)gr < HH && (unsigned)gc < WW)
            v = g_x[src][ch][gr * WW + gc];
        tile[ch][r][c] = v;
    }
    __syncthreads();

    int tx = tid % TILE, ty = tid / TILE;

    // ---- conv3x3: 16 packed accumulators = 32 hidden channels ----
    u64 acc[16];
    {
        const ulonglong2* bp = (const ulonglong2*)&c_pack[B1P];
        #pragma unroll
        for (int k = 0; k < 8; k++) { ulonglong2 v = bp[k]; acc[2*k] = v.x; acc[2*k+1] = v.y; }
    }

    #pragma unroll 1
    for (int ci = 0; ci < C_IN; ci++) {
        #pragma unroll
        for (int ky = 0; ky < 3; ky++) {
            const float* trow = &tile[ci][ty + ky][tx];
            #pragma unroll
            for (int kx = 0; kx < 3; kx++) {
                u64 xd = dup2(trow[kx]);
                const ulonglong2* wp = (const ulonglong2*)&c_pack[W1P + (ci * 9 + ky * 3 + kx) * 32];
                #pragma unroll
                for (int j = 0; j < 8; j++) {
                    ulonglong2 w = wp[j];            // 16B constant-port load: 4 weights
                    acc[2*j]   = fma2(xd, w.x, acc[2*j]);
                    acc[2*j+1] = fma2(xd, w.y, acc[2*j+1]);
                }
            }
        }
    }

    // ---- gelu (exact erf) + conv1x1, all in registers ----
    u64 dxp[4];
    {
        const ulonglong2* bp = (const ulonglong2*)&c_pack[B2P];
        ulonglong2 v0 = bp[0], v1 = bp[1];
        dxp[0] = v0.x; dxp[1] = v0.y; dxp[2] = v1.x; dxp[3] = v1.y;
    }
    #pragma unroll
    for (int j = 0; j < 16; j++) {
        float h0, h1;
        unpack2(acc[j], h0, h1);
        float g0 = 0.5f * h0 * (1.0f + erff(h0 * 0.7071067811865476f));
        float g1 = 0.5f * h1 * (1.0f + erff(h1 * 0.7071067811865476f));
        u64 g0d = dup2(g0), g1d = dup2(g1);
        {
            const ulonglong2* wp = (const ulonglong2*)&c_pack[W2P + (2*j) * 8];
            ulonglong2 wa = wp[0], wb = wp[1];
            dxp[0] = fma2(g0d, wa.x, dxp[0]);
            dxp[1] = fma2(g0d, wa.y, dxp[1]);
            dxp[2] = fma2(g0d, wb.x, dxp[2]);
            dxp[3] = fma2(g0d, wb.y, dxp[3]);
        }
        {
            const ulonglong2* wp = (const ulonglong2*)&c_pack[W2P + (2*j+1) * 8];
            ulonglong2 wa = wp[0], wb = wp[1];
            dxp[0] = fma2(g1d, wa.x, dxp[0]);
            dxp[1] = fma2(g1d, wa.y, dxp[1]);
            dxp[2] = fma2(g1d, wb.x, dxp[2]);
            dxp[3] = fma2(g1d, wb.y, dxp[3]);
        }
    }

    // ---- masked update ----
    int row = row0 + ty, col = col0 + tx;
    int p = row * WW + col;
    unsigned bits = g_mask[iter][p >> 5];
    float m = ((bits >> (p & 31)) & 1u) ? 0.1f : 0.0f;   // fold 0.1 into the mask
    int dst = src ^ 1;
    #pragma unroll
    for (int k = 0; k < 4; k++) {
        float d0, d1;
        unpack2(dxp[k], d0, d1);
        g_x[dst][2*k][p]   = tile[2*k][ty + 1][tx + 1]   + d0 * m;
        g_x[dst][2*k+1][p] = tile[2*k+1][ty + 1][tx + 1] + d1 * m;
    }
}

// ---------------- projection ----------------
__global__ void project_kernel(const float* __restrict__ Wp, const float* __restrict__ bp,
                               float* __restrict__ out) {
    int p = blockIdx.x * blockDim.x + threadIdx.x;
    if (p >= NPIX) return;
    float s = bp[0];
    #pragma unroll
    for (int ch = 0; ch < C_IN; ch++) s += g_x[0][ch][p] * Wp[ch];
    out[p] = s;
}

extern "C" void kernel_launch(void* const* d_in, const int* in_sizes, int n_in,
                              void* d_out, int out_size) {
    const float* seed = (const float*)d_in[0];
    const float* W1   = (const float*)d_in[1];
    const float* b1   = (const float*)d_in[2];
    const float* W2   = (const float*)d_in[3];
    const float* b2   = (const float*)d_in[4];
    const float* Wp   = (const float*)d_in[5];
    const float* bp   = (const float*)d_in[6];
    float* out = (float*)d_out;

    repack_kernel<<<(2600 + 255) / 256, 256>>>(W1, b1, W2, b2);
    // D2D copy of the repacked weights into constant memory (graph-capturable memcpy node)
    {
        const void* src_dev;
        cudaGetSymbolAddress((void**)&src_dev, g_pack);
        cudaMemcpyToSymbolAsync(c_pack, src_dev, sizeof(float) * (2304 + 256 + 32 + 8),
                                0, cudaMemcpyDeviceToDevice, 0);
    }

    upsample_kernel<<<(C_IN * NPIX + 255) / 256, 256>>>(seed);
    genmask_kernel<<<(NIT * 32768) / 256, 256>>>();

    dim3 grid(WW / TILE, HH / TILE);
    for (int s = 0; s < NIT; s++)
        step_kernel<<<grid, 256>>>(s & 1, s);
    // after 64 steps the result is back in buffer 0
    project_kernel<<<(NPIX + 255) / 256, 256>>>(Wp, bp, out);
}